// round 13
// baseline (speedup 1.0000x reference)
#include <cuda_runtime.h>
#include <cstdint>

// One exact wave on B200: 148 SMs x 8 resident blocks (256 thr, 32 regs).
// Grid-stride interleaved sweep + __ldcs + L2 prefetch 8 strides ahead.
#define NBLOCKS 1184
#define NTHREADS 256
#define PF_DIST 8
#define EPS 1e-7

// Static scratch (no dynamic allocation allowed).
__device__ float g_S  [NBLOCKS];   // sum of c = min(p, 1-p) over all elements
__device__ float g_S1 [NBLOCKS];   // sum of c over label-1 elements
__device__ float g_N1 [NBLOCKS];   // count of label-1 elements
__device__ unsigned int g_done = 0;

// Per element (label t in {0,1}, pred p):  c = min(p, 1-p) = yp[0].
//   S += c;  S1 += t ? c : 0;  n1 += t
// TP0 = S - S1, TP1 = n1 - S1; all confusion-matrix terms derive from these.
__global__ __launch_bounds__(NTHREADS, 8) void f1_fused_kernel(
    const float4* __restrict__ pred4,
    const int4*  __restrict__ lab4,
    int nvec,
    int n_total,
    float* __restrict__ out)
{
    float S = 0.0f, S1 = 0.0f;
    int n1 = 0;

    const int stride = gridDim.x * blockDim.x;
    const bool pf_lane = ((threadIdx.x & 7) == 0);  // one prefetch per 128B line

    for (int i = blockIdx.x * blockDim.x + threadIdx.x; i < nvec; i += stride) {
        // Fire-and-forget L2 prefetch PF_DIST strides ahead. Keeps the DRAM
        // queues fed independent of warp scoreboard stalls; demand loads then
        // hit L2 instead of DRAM.
        int pf = i + PF_DIST * stride;
        if (pf_lane && pf < nvec) {
            asm volatile("prefetch.global.L2 [%0];" :: "l"(pred4 + pf));
            asm volatile("prefetch.global.L2 [%0];" :: "l"(lab4 + pf));
        }

        float4 p = __ldcs(&pred4[i]);   // evict-first streaming load
        int4   t = __ldcs(&lab4[i]);

        float c0 = fminf(p.x, 1.0f - p.x);
        float c1 = fminf(p.y, 1.0f - p.y);
        float c2 = fminf(p.z, 1.0f - p.z);
        float c3 = fminf(p.w, 1.0f - p.w);

        S  += (c0 + c1) + (c2 + c3);
        S1 += ((t.x ? c0 : 0.0f) + (t.y ? c1 : 0.0f))
            + ((t.z ? c2 : 0.0f) + (t.w ? c3 : 0.0f));
        n1 += (t.x + t.y) + (t.z + t.w);
    }

    // Scalar tail (n_total % 4) — block 0 thread 0 only.
    if (blockIdx.x == 0 && threadIdx.x == 0) {
        const float* pred = (const float*)pred4;
        const int*   lab  = (const int*)lab4;
        for (int k = nvec * 4; k < n_total; k++) {
            float pp = pred[k];
            float c = fminf(pp, 1.0f - pp);
            S += c;
            if (lab[k]) { S1 += c; n1++; }
        }
    }

    // ---- block reduce ----
    float fn1 = (float)n1;
    #pragma unroll
    for (int off = 16; off > 0; off >>= 1) {
        S   += __shfl_down_sync(0xFFFFFFFFu, S,   off);
        S1  += __shfl_down_sync(0xFFFFFFFFu, S1,  off);
        fn1 += __shfl_down_sync(0xFFFFFFFFu, fn1, off);
    }

    __shared__ float sS [NTHREADS / 32];
    __shared__ float sS1[NTHREADS / 32];
    __shared__ float sN1[NTHREADS / 32];
    int lane = threadIdx.x & 31;
    int wid  = threadIdx.x >> 5;
    if (lane == 0) { sS[wid] = S; sS1[wid] = S1; sN1[wid] = fn1; }
    __syncthreads();

    if (wid == 0) {
        S   = (lane < NTHREADS / 32) ? sS [lane] : 0.0f;
        S1  = (lane < NTHREADS / 32) ? sS1[lane] : 0.0f;
        fn1 = (lane < NTHREADS / 32) ? sN1[lane] : 0.0f;
        #pragma unroll
        for (int off = 16; off > 0; off >>= 1) {
            S   += __shfl_down_sync(0xFFFFFFFFu, S,   off);
            S1  += __shfl_down_sync(0xFFFFFFFFu, S1,  off);
            fn1 += __shfl_down_sync(0xFFFFFFFFu, fn1, off);
        }
        if (lane == 0) {
            g_S [blockIdx.x] = S;
            g_S1[blockIdx.x] = S1;
            g_N1[blockIdx.x] = fn1;
        }
    }

    // ---- last-block finalization ----
    __shared__ bool is_last;
    __threadfence();
    if (threadIdx.x == 0) {
        unsigned int prev = atomicAdd(&g_done, 1u);
        is_last = (prev == (unsigned int)(gridDim.x - 1));
    }
    __syncthreads();
    if (!is_last) return;

    double dS = 0.0, dS1 = 0.0, dN1 = 0.0;
    for (int k = threadIdx.x; k < NBLOCKS; k += NTHREADS) {
        dS  += (double)g_S [k];
        dS1 += (double)g_S1[k];
        dN1 += (double)g_N1[k];
    }

    __shared__ double s0[NTHREADS], s1d[NTHREADS], s2[NTHREADS];
    s0[threadIdx.x] = dS; s1d[threadIdx.x] = dS1; s2[threadIdx.x] = dN1;
    __syncthreads();
    for (int off = NTHREADS / 2; off > 0; off >>= 1) {
        if (threadIdx.x < off) {
            s0 [threadIdx.x] += s0 [threadIdx.x + off];
            s1d[threadIdx.x] += s1d[threadIdx.x + off];
            s2 [threadIdx.x] += s2 [threadIdx.x + off];
        }
        __syncthreads();
    }

    if (threadIdx.x == 0) {
        double St = s0[0], St1 = s1d[0], N1 = s2[0];
        double N0 = (double)n_total - N1;

        double TP0 = St - St1;      // label-0 yp[0] mass
        double TP1 = N1 - St1;      // label-1 yp[1] mass

        double fn0 = N0 - TP0;
        double fn1d = N1 - TP1;
        double fp0 = fn1d;
        double fp1 = fn0;

        double p0 = TP0 / (TP0 + fp0 + EPS);
        double r0 = TP0 / (TP0 + fn0 + EPS);
        double f1_0 = 2.0 * p0 * r0 / (p0 + r0 + EPS);

        double p1 = TP1 / (TP1 + fp1 + EPS);
        double r1 = TP1 / (TP1 + fn1d + EPS);
        double f1_1 = 2.0 * p1 * r1 / (p1 + r1 + EPS);

        f1_0 = fmin(fmax(f1_0, EPS), 1.0 - EPS);
        f1_1 = fmin(fmax(f1_1, EPS), 1.0 - EPS);

        out[0] = (float)(1.0 - 0.5 * (f1_0 + f1_1));
        g_done = 0;   // reset for next graph replay
    }
}

extern "C" void kernel_launch(void* const* d_in, const int* in_sizes, int n_in,
                              void* d_out, int out_size)
{
    const float* y_pred = (const float*)d_in[0];
    const int*   y_true = (const int*)d_in[1];   // jnp.int64 w/o x64 -> int32
    int n = in_sizes[0];
    int nvec = n / 4;

    f1_fused_kernel<<<NBLOCKS, NTHREADS>>>(
        (const float4*)y_pred, (const int4*)y_true, nvec, n, (float*)d_out);
}

// round 14
// speedup vs baseline: 1.1502x; 1.1502x over previous
#include <cuda_runtime.h>
#include <cstdint>

// One exact wave on B200: 148 SMs x 8 resident blocks (256 thr, 32 regs).
// Grid-stride interleaved sweep + __ldcs + L2 prefetch 2 strides ahead.
// PF_DIST curve so far: 0 -> 47.1us, 4 -> 45.0us, 8 -> 49.5us (L2 thrash).
#define NBLOCKS 1184
#define NTHREADS 256
#define PF_DIST 2
#define EPS 1e-7

// Static scratch (no dynamic allocation allowed).
__device__ float g_S  [NBLOCKS];   // sum of c = min(p, 1-p) over all elements
__device__ float g_S1 [NBLOCKS];   // sum of c over label-1 elements
__device__ float g_N1 [NBLOCKS];   // count of label-1 elements
__device__ unsigned int g_done = 0;

// Per element (label t in {0,1}, pred p):  c = min(p, 1-p) = yp[0].
//   S += c;  S1 += t ? c : 0;  n1 += t
// TP0 = S - S1, TP1 = n1 - S1; all confusion-matrix terms derive from these.
__global__ __launch_bounds__(NTHREADS, 8) void f1_fused_kernel(
    const float4* __restrict__ pred4,
    const int4*  __restrict__ lab4,
    int nvec,
    int n_total,
    float* __restrict__ out)
{
    float S = 0.0f, S1 = 0.0f;
    int n1 = 0;

    const int stride = gridDim.x * blockDim.x;
    const bool pf_lane = ((threadIdx.x & 7) == 0);  // one prefetch per 128B line

    for (int i = blockIdx.x * blockDim.x + threadIdx.x; i < nvec; i += stride) {
        // Fire-and-forget L2 prefetch PF_DIST strides ahead. Keeps the DRAM
        // queues fed independent of warp scoreboard stalls; demand loads then
        // hit L2 instead of DRAM.
        int pf = i + PF_DIST * stride;
        if (pf_lane && pf < nvec) {
            asm volatile("prefetch.global.L2 [%0];" :: "l"(pred4 + pf));
            asm volatile("prefetch.global.L2 [%0];" :: "l"(lab4 + pf));
        }

        float4 p = __ldcs(&pred4[i]);   // evict-first streaming load
        int4   t = __ldcs(&lab4[i]);

        float c0 = fminf(p.x, 1.0f - p.x);
        float c1 = fminf(p.y, 1.0f - p.y);
        float c2 = fminf(p.z, 1.0f - p.z);
        float c3 = fminf(p.w, 1.0f - p.w);

        S  += (c0 + c1) + (c2 + c3);
        S1 += ((t.x ? c0 : 0.0f) + (t.y ? c1 : 0.0f))
            + ((t.z ? c2 : 0.0f) + (t.w ? c3 : 0.0f));
        n1 += (t.x + t.y) + (t.z + t.w);
    }

    // Scalar tail (n_total % 4) — block 0 thread 0 only.
    if (blockIdx.x == 0 && threadIdx.x == 0) {
        const float* pred = (const float*)pred4;
        const int*   lab  = (const int*)lab4;
        for (int k = nvec * 4; k < n_total; k++) {
            float pp = pred[k];
            float c = fminf(pp, 1.0f - pp);
            S += c;
            if (lab[k]) { S1 += c; n1++; }
        }
    }

    // ---- block reduce ----
    float fn1 = (float)n1;
    #pragma unroll
    for (int off = 16; off > 0; off >>= 1) {
        S   += __shfl_down_sync(0xFFFFFFFFu, S,   off);
        S1  += __shfl_down_sync(0xFFFFFFFFu, S1,  off);
        fn1 += __shfl_down_sync(0xFFFFFFFFu, fn1, off);
    }

    __shared__ float sS [NTHREADS / 32];
    __shared__ float sS1[NTHREADS / 32];
    __shared__ float sN1[NTHREADS / 32];
    int lane = threadIdx.x & 31;
    int wid  = threadIdx.x >> 5;
    if (lane == 0) { sS[wid] = S; sS1[wid] = S1; sN1[wid] = fn1; }
    __syncthreads();

    if (wid == 0) {
        S   = (lane < NTHREADS / 32) ? sS [lane] : 0.0f;
        S1  = (lane < NTHREADS / 32) ? sS1[lane] : 0.0f;
        fn1 = (lane < NTHREADS / 32) ? sN1[lane] : 0.0f;
        #pragma unroll
        for (int off = 16; off > 0; off >>= 1) {
            S   += __shfl_down_sync(0xFFFFFFFFu, S,   off);
            S1  += __shfl_down_sync(0xFFFFFFFFu, S1,  off);
            fn1 += __shfl_down_sync(0xFFFFFFFFu, fn1, off);
        }
        if (lane == 0) {
            g_S [blockIdx.x] = S;
            g_S1[blockIdx.x] = S1;
            g_N1[blockIdx.x] = fn1;
        }
    }

    // ---- last-block finalization ----
    __shared__ bool is_last;
    __threadfence();
    if (threadIdx.x == 0) {
        unsigned int prev = atomicAdd(&g_done, 1u);
        is_last = (prev == (unsigned int)(gridDim.x - 1));
    }
    __syncthreads();
    if (!is_last) return;

    double dS = 0.0, dS1 = 0.0, dN1 = 0.0;
    for (int k = threadIdx.x; k < NBLOCKS; k += NTHREADS) {
        dS  += (double)g_S [k];
        dS1 += (double)g_S1[k];
        dN1 += (double)g_N1[k];
    }

    __shared__ double s0[NTHREADS], s1d[NTHREADS], s2[NTHREADS];
    s0[threadIdx.x] = dS; s1d[threadIdx.x] = dS1; s2[threadIdx.x] = dN1;
    __syncthreads();
    for (int off = NTHREADS / 2; off > 0; off >>= 1) {
        if (threadIdx.x < off) {
            s0 [threadIdx.x] += s0 [threadIdx.x + off];
            s1d[threadIdx.x] += s1d[threadIdx.x + off];
            s2 [threadIdx.x] += s2 [threadIdx.x + off];
        }
        __syncthreads();
    }

    if (threadIdx.x == 0) {
        double St = s0[0], St1 = s1d[0], N1 = s2[0];
        double N0 = (double)n_total - N1;

        double TP0 = St - St1;      // label-0 yp[0] mass
        double TP1 = N1 - St1;      // label-1 yp[1] mass

        double fn0 = N0 - TP0;
        double fn1d = N1 - TP1;
        double fp0 = fn1d;
        double fp1 = fn0;

        double p0 = TP0 / (TP0 + fp0 + EPS);
        double r0 = TP0 / (TP0 + fn0 + EPS);
        double f1_0 = 2.0 * p0 * r0 / (p0 + r0 + EPS);

        double p1 = TP1 / (TP1 + fp1 + EPS);
        double r1 = TP1 / (TP1 + fn1d + EPS);
        double f1_1 = 2.0 * p1 * r1 / (p1 + r1 + EPS);

        f1_0 = fmin(fmax(f1_0, EPS), 1.0 - EPS);
        f1_1 = fmin(fmax(f1_1, EPS), 1.0 - EPS);

        out[0] = (float)(1.0 - 0.5 * (f1_0 + f1_1));
        g_done = 0;   // reset for next graph replay
    }
}

extern "C" void kernel_launch(void* const* d_in, const int* in_sizes, int n_in,
                              void* d_out, int out_size)
{
    const float* y_pred = (const float*)d_in[0];
    const int*   y_true = (const int*)d_in[1];   // jnp.int64 w/o x64 -> int32
    int n = in_sizes[0];
    int nvec = n / 4;

    f1_fused_kernel<<<NBLOCKS, NTHREADS>>>(
        (const float4*)y_pred, (const int4*)y_true, nvec, n, (float*)d_out);
}

// round 15
// speedup vs baseline: 1.2114x; 1.0532x over previous
#include <cuda_runtime.h>
#include <cstdint>

// One exact wave on B200: 148 SMs x 8 resident blocks (256 thr, 32 regs).
// Grid-stride interleaved sweep + __ldcs + L2 prefetch 1 stride ahead.
// PF_DIST curve: 0 -> 47.1us, 2 -> 43.0us, 4 -> 45.0us, 8 -> 49.5us.
#define NBLOCKS 1184
#define NTHREADS 256
#define PF_DIST 1
#define EPS 1e-7

// Static scratch (no dynamic allocation allowed).
__device__ float g_S  [NBLOCKS];   // sum of c = min(p, 1-p) over all elements
__device__ float g_S1 [NBLOCKS];   // sum of c over label-1 elements
__device__ float g_N1 [NBLOCKS];   // count of label-1 elements
__device__ unsigned int g_done = 0;

// Per element (label t in {0,1}, pred p):  c = min(p, 1-p) = yp[0].
//   S += c;  S1 += t ? c : 0;  n1 += t
// TP0 = S - S1, TP1 = n1 - S1; all confusion-matrix terms derive from these.
__global__ __launch_bounds__(NTHREADS, 8) void f1_fused_kernel(
    const float4* __restrict__ pred4,
    const int4*  __restrict__ lab4,
    int nvec,
    int n_total,
    float* __restrict__ out)
{
    float S = 0.0f, S1 = 0.0f;
    int n1 = 0;

    const int stride = gridDim.x * blockDim.x;
    const bool pf_lane = ((threadIdx.x & 7) == 0);  // one prefetch per 128B line

    for (int i = blockIdx.x * blockDim.x + threadIdx.x; i < nvec; i += stride) {
        // Fire-and-forget L2 prefetch PF_DIST strides ahead. Keeps the DRAM
        // queues fed independent of warp scoreboard stalls; demand loads then
        // hit L2 instead of DRAM.
        int pf = i + PF_DIST * stride;
        if (pf_lane && pf < nvec) {
            asm volatile("prefetch.global.L2 [%0];" :: "l"(pred4 + pf));
            asm volatile("prefetch.global.L2 [%0];" :: "l"(lab4 + pf));
        }

        float4 p = __ldcs(&pred4[i]);   // evict-first streaming load
        int4   t = __ldcs(&lab4[i]);

        float c0 = fminf(p.x, 1.0f - p.x);
        float c1 = fminf(p.y, 1.0f - p.y);
        float c2 = fminf(p.z, 1.0f - p.z);
        float c3 = fminf(p.w, 1.0f - p.w);

        S  += (c0 + c1) + (c2 + c3);
        S1 += ((t.x ? c0 : 0.0f) + (t.y ? c1 : 0.0f))
            + ((t.z ? c2 : 0.0f) + (t.w ? c3 : 0.0f));
        n1 += (t.x + t.y) + (t.z + t.w);
    }

    // Scalar tail (n_total % 4) — block 0 thread 0 only.
    if (blockIdx.x == 0 && threadIdx.x == 0) {
        const float* pred = (const float*)pred4;
        const int*   lab  = (const int*)lab4;
        for (int k = nvec * 4; k < n_total; k++) {
            float pp = pred[k];
            float c = fminf(pp, 1.0f - pp);
            S += c;
            if (lab[k]) { S1 += c; n1++; }
        }
    }

    // ---- block reduce ----
    float fn1 = (float)n1;
    #pragma unroll
    for (int off = 16; off > 0; off >>= 1) {
        S   += __shfl_down_sync(0xFFFFFFFFu, S,   off);
        S1  += __shfl_down_sync(0xFFFFFFFFu, S1,  off);
        fn1 += __shfl_down_sync(0xFFFFFFFFu, fn1, off);
    }

    __shared__ float sS [NTHREADS / 32];
    __shared__ float sS1[NTHREADS / 32];
    __shared__ float sN1[NTHREADS / 32];
    int lane = threadIdx.x & 31;
    int wid  = threadIdx.x >> 5;
    if (lane == 0) { sS[wid] = S; sS1[wid] = S1; sN1[wid] = fn1; }
    __syncthreads();

    if (wid == 0) {
        S   = (lane < NTHREADS / 32) ? sS [lane] : 0.0f;
        S1  = (lane < NTHREADS / 32) ? sS1[lane] : 0.0f;
        fn1 = (lane < NTHREADS / 32) ? sN1[lane] : 0.0f;
        #pragma unroll
        for (int off = 16; off > 0; off >>= 1) {
            S   += __shfl_down_sync(0xFFFFFFFFu, S,   off);
            S1  += __shfl_down_sync(0xFFFFFFFFu, S1,  off);
            fn1 += __shfl_down_sync(0xFFFFFFFFu, fn1, off);
        }
        if (lane == 0) {
            g_S [blockIdx.x] = S;
            g_S1[blockIdx.x] = S1;
            g_N1[blockIdx.x] = fn1;
        }
    }

    // ---- last-block finalization ----
    __shared__ bool is_last;
    __threadfence();
    if (threadIdx.x == 0) {
        unsigned int prev = atomicAdd(&g_done, 1u);
        is_last = (prev == (unsigned int)(gridDim.x - 1));
    }
    __syncthreads();
    if (!is_last) return;

    double dS = 0.0, dS1 = 0.0, dN1 = 0.0;
    for (int k = threadIdx.x; k < NBLOCKS; k += NTHREADS) {
        dS  += (double)g_S [k];
        dS1 += (double)g_S1[k];
        dN1 += (double)g_N1[k];
    }

    __shared__ double s0[NTHREADS], s1d[NTHREADS], s2[NTHREADS];
    s0[threadIdx.x] = dS; s1d[threadIdx.x] = dS1; s2[threadIdx.x] = dN1;
    __syncthreads();
    for (int off = NTHREADS / 2; off > 0; off >>= 1) {
        if (threadIdx.x < off) {
            s0 [threadIdx.x] += s0 [threadIdx.x + off];
            s1d[threadIdx.x] += s1d[threadIdx.x + off];
            s2 [threadIdx.x] += s2 [threadIdx.x + off];
        }
        __syncthreads();
    }

    if (threadIdx.x == 0) {
        double St = s0[0], St1 = s1d[0], N1 = s2[0];
        double N0 = (double)n_total - N1;

        double TP0 = St - St1;      // label-0 yp[0] mass
        double TP1 = N1 - St1;      // label-1 yp[1] mass

        double fn0 = N0 - TP0;
        double fn1d = N1 - TP1;
        double fp0 = fn1d;
        double fp1 = fn0;

        double p0 = TP0 / (TP0 + fp0 + EPS);
        double r0 = TP0 / (TP0 + fn0 + EPS);
        double f1_0 = 2.0 * p0 * r0 / (p0 + r0 + EPS);

        double p1 = TP1 / (TP1 + fp1 + EPS);
        double r1 = TP1 / (TP1 + fn1d + EPS);
        double f1_1 = 2.0 * p1 * r1 / (p1 + r1 + EPS);

        f1_0 = fmin(fmax(f1_0, EPS), 1.0 - EPS);
        f1_1 = fmin(fmax(f1_1, EPS), 1.0 - EPS);

        out[0] = (float)(1.0 - 0.5 * (f1_0 + f1_1));
        g_done = 0;   // reset for next graph replay
    }
}

extern "C" void kernel_launch(void* const* d_in, const int* in_sizes, int n_in,
                              void* d_out, int out_size)
{
    const float* y_pred = (const float*)d_in[0];
    const int*   y_true = (const int*)d_in[1];   // jnp.int64 w/o x64 -> int32
    int n = in_sizes[0];
    int nvec = n / 4;

    f1_fused_kernel<<<NBLOCKS, NTHREADS>>>(
        (const float4*)y_pred, (const int4*)y_true, nvec, n, (float*)d_out);
}